// round 4
// baseline (speedup 1.0000x reference)
#include <cuda_runtime.h>
#include <math.h>

#define BB 1536
#define NG 64
#define NP 24
#define ED 64
#define HD 128
#define SEQ 12

// ---------------- scratch (static device globals; no allocation) -------------
__device__ __align__(16) float g_h[BB*HD];
__device__ __align__(16) float g_c[BB*HD];
__device__ __align__(16) float g_hl[BB*HD];
__device__ __align__(16) float g_lp[BB*2];
__device__ __align__(16) float g_decin[BB*ED];
__device__ __align__(16) float g_hcon[BB*512];   // h @ Wp1_h^T + combined bias
__device__ __align__(16) float g_pool[BB*1024];
__device__ __align__(16) float g_mh[BB*1024];
__device__ __align__(16) float g_M0[512];
__device__ __align__(16) float g_M1[512];
__device__ __align__(16) float g_biasc[512];
__device__ __align__(16) float g_WihT[64*512];
__device__ __align__(16) float g_WhhT[128*512];
// pre-split (hi,lo) operands
__device__ __align__(16) float2 g_Ahl[36864*512];     // pool A matrix, per step
__device__ __align__(16) float2 g_Wp2hl[1024*512];
__device__ __align__(16) float2 g_Wm1hl[1024*1152];
__device__ __align__(16) float2 g_Wm2hl[128*1024];
__device__ __align__(16) float2 g_Wp1hhl[512*128];

// ---------------- tf32 helpers ------------------------------------------------
__device__ __forceinline__ float2 split_tf32(float v) {
    unsigned hu; asm("cvt.rna.tf32.f32 %0, %1;" : "=r"(hu) : "f"(v));
    float hi = __uint_as_float(hu);
    float rem = v - hi;
    unsigned lu; asm("cvt.rna.tf32.f32 %0, %1;" : "=r"(lu) : "f"(rem));
    return make_float2(hi, __uint_as_float(lu));
}

__device__ __forceinline__ void mma8(float* c, float a0, float a1, float a2, float a3,
                                     float b0, float b1) {
    asm("mma.sync.aligned.m16n8k8.row.col.f32.tf32.tf32.f32 "
        "{%0,%1,%2,%3},{%4,%5,%6,%7},{%8,%9},{%0,%1,%2,%3};"
        : "+f"(c[0]), "+f"(c[1]), "+f"(c[2]), "+f"(c[3])
        : "r"(__float_as_uint(a0)), "r"(__float_as_uint(a1)),
          "r"(__float_as_uint(a2)), "r"(__float_as_uint(a3)),
          "r"(__float_as_uint(b0)), "r"(__float_as_uint(b1)));
}

__device__ __forceinline__ void mma3(float* c, const float2* a, const float2* b) {
    mma8(c, a[0].x, a[1].x, a[2].x, a[3].x, b[0].x, b[1].x);
    mma8(c, a[0].x, a[1].x, a[2].x, a[3].x, b[0].y, b[1].y);
    mma8(c, a[0].y, a[1].y, a[2].y, a[3].y, b[0].x, b[1].x);
}

// ---------------- precompute --------------------------------------------------
__global__ void precompute_kernel(const float* __restrict__ Wih,
                                  const float* __restrict__ Whh,
                                  const float* __restrict__ Wp1,
                                  const float* __restrict__ Wp_emb,
                                  const float* __restrict__ bp_emb,
                                  const float* __restrict__ bp1) {
    int idx = blockIdx.x * blockDim.x + threadIdx.x;
    if (idx < 512*64)  { int r = idx/64,  c = idx%64;  g_WihT[c*512 + r] = Wih[idx]; }
    if (idx < 512*128) { int r = idx/128, c = idx%128; g_WhhT[c*512 + r] = Whh[idx]; }
    if (idx < 512) {
        float m0 = 0.f, m1 = 0.f, bc = 0.f;
        for (int e = 0; e < 64; e++) {
            float w = Wp1[idx*192 + e];
            m0 += w * Wp_emb[e*2 + 0];
            m1 += w * Wp_emb[e*2 + 1];
            bc += w * bp_emb[e];
        }
        g_M0[idx] = m0;
        g_M1[idx] = m1;
        g_biasc[idx] = bp1[idx] + bc;
    }
}

// split all weight matrices once per launch
__global__ void splitw_kernel(const float* __restrict__ Wp1,
                              const float* __restrict__ Wp2,
                              const float* __restrict__ Wm1,
                              const float* __restrict__ Wm2) {
    int idx = blockIdx.x * blockDim.x + threadIdx.x;
    if (idx < 512*128)  g_Wp1hhl[idx] = split_tf32(Wp1[(idx >> 7)*192 + 64 + (idx & 127)]);
    if (idx < 1024*512) g_Wp2hl[idx]  = split_tf32(Wp2[idx]);
    if (idx < 1024*1152) g_Wm1hl[idx] = split_tf32(Wm1[idx]);
    if (idx < 128*1024) g_Wm2hl[idx]  = split_tf32(Wm2[idx]);
}

// ---------------- init --------------------------------------------------------
__global__ void init_kernel(const float* __restrict__ h0, const float* __restrict__ c0,
                            const float* __restrict__ lp, const float* __restrict__ lpr,
                            const float* __restrict__ Wemb, const float* __restrict__ bemb) {
    int idx = blockIdx.x * blockDim.x + threadIdx.x;
    if (idx < BB*HD) { g_h[idx] = h0[idx]; g_c[idx] = c0[idx]; }
    if (idx < BB*2)  { g_lp[idx] = lp[idx]; }
    if (idx < BB*ED) {
        int b = idx / ED, e = idx % ED;
        g_decin[idx] = lpr[b*2]*Wemb[e*2] + lpr[b*2+1]*Wemb[e*2+1] + bemb[e];
    }
}

// ---------------- fused LSTM step ---------------------------------------------
__global__ void lstm_kernel(const float* __restrict__ bih, const float* __restrict__ bhh) {
    int tid = threadIdx.x;
    int u = tid & 127;
    int rh = tid >> 7;
    int r0 = blockIdx.x * 8;
    __shared__ float xs[8][64];
    __shared__ float hs[8][128];
    for (int l = tid; l < 8*64;  l += 256) xs[l>>6][l&63]  = g_decin[r0*64  + l];
    for (int l = tid; l < 8*128; l += 256) hs[l>>7][l&127] = g_h[r0*128 + l];
    __syncthreads();

    float acc[4][4];
    #pragma unroll
    for (int gt = 0; gt < 4; gt++) {
        float bb = bih[u + gt*128] + bhh[u + gt*128];
        #pragma unroll
        for (int r = 0; r < 4; r++) acc[gt][r] = bb;
    }
    for (int e = 0; e < 64; e++) {
        float w0 = g_WihT[e*512 + u];
        float w1 = g_WihT[e*512 + u + 128];
        float w2 = g_WihT[e*512 + u + 256];
        float w3 = g_WihT[e*512 + u + 384];
        #pragma unroll
        for (int r = 0; r < 4; r++) {
            float x = xs[rh*4 + r][e];
            acc[0][r] += w0*x; acc[1][r] += w1*x; acc[2][r] += w2*x; acc[3][r] += w3*x;
        }
    }
    for (int e = 0; e < 128; e++) {
        float w0 = g_WhhT[e*512 + u];
        float w1 = g_WhhT[e*512 + u + 128];
        float w2 = g_WhhT[e*512 + u + 256];
        float w3 = g_WhhT[e*512 + u + 384];
        #pragma unroll
        for (int r = 0; r < 4; r++) {
            float x = hs[rh*4 + r][e];
            acc[0][r] += w0*x; acc[1][r] += w1*x; acc[2][r] += w2*x; acc[3][r] += w3*x;
        }
    }
    #pragma unroll
    for (int r = 0; r < 4; r++) {
        int row = r0 + rh*4 + r;
        float ig = 1.f / (1.f + __expf(-acc[0][r]));
        float fg = 1.f / (1.f + __expf(-acc[1][r]));
        float gg = tanhf(acc[2][r]);
        float og = 1.f / (1.f + __expf(-acc[3][r]));
        int bi = row*128 + u;
        float cc = fg * g_c[bi] + ig * gg;
        g_c[bi]  = cc;
        g_hl[bi] = og * tanhf(cc);
    }
}

// ---------------- rel_pos, position update, rels output, next dec_in ---------
__global__ void posdec_kernel(const float* __restrict__ Wpos, const float* __restrict__ bpos,
                              const float* __restrict__ Wemb, const float* __restrict__ bemb,
                              float* __restrict__ rels_out, int step) {
    int b = blockIdx.x;
    int t = threadIdx.x;
    __shared__ float hr[128];
    __shared__ float sr[2];
    hr[t] = g_hl[b*128 + t];
    __syncthreads();
    int w = t >> 5, lane = t & 31;
    if (w < 2) {
        float part = 0.f;
        for (int k = lane; k < 128; k += 32) part += hr[k] * Wpos[w*128 + k];
        #pragma unroll
        for (int off = 16; off; off >>= 1) part += __shfl_down_sync(0xffffffffu, part, off);
        if (lane == 0) sr[w] = part + bpos[w];
    }
    __syncthreads();
    float ra = sr[0], rb = sr[1];
    if (t < 64) g_decin[b*64 + t] = ra*Wemb[t*2] + rb*Wemb[t*2+1] + bemb[t];
    if (t == 0) {
        rels_out[(step*BB + b)*2 + 0] = ra;
        rels_out[(step*BB + b)*2 + 1] = rb;
        g_lp[b*2 + 0] += ra;
        g_lp[b*2 + 1] += rb;
    }
}

// ---------------- per-step A-matrix build + split (pool layer-1 fused) -------
// one block per row of the 36864x512 A matrix; 128 threads x 4 k's each.
__global__ void asplit_kernel() {
    int row = blockIdx.x;
    int grp = row / 576;
    int rem = row - grp*576;
    int i = rem / 24, j = rem - (rem/24)*24;
    int t = threadIdx.x;
    float pix = g_lp[(grp*24 + i)*2 + 0];
    float piy = g_lp[(grp*24 + i)*2 + 1];
    float pjx = g_lp[(grp*24 + j)*2 + 0];
    float pjy = g_lp[(grp*24 + j)*2 + 1];
    float dx = pjx - pix, dy = pjy - piy;
    float inv = 1.f / fmaxf(sqrtf(dx*dx + dy*dy), 1e-12f);
    float ra = dx * inv, rb = dy * inv;
    int k = t * 4;
    const float4 hc = *(const float4*)&g_hcon[(grp*24 + j)*512 + k];
    const float4 m0 = *(const float4*)&g_M0[k];
    const float4 m1 = *(const float4*)&g_M1[k];
    float2* dst = &g_Ahl[row*512 + k];
    dst[0] = split_tf32(fmaxf(fmaf(ra, m0.x, fmaf(rb, m1.x, hc.x)), 0.f));
    dst[1] = split_tf32(fmaxf(fmaf(ra, m0.y, fmaf(rb, m1.y, hc.y)), 0.f));
    dst[2] = split_tf32(fmaxf(fmaf(ra, m0.z, fmaf(rb, m1.z, hc.z)), 0.f));
    dst[3] = split_tf32(fmaxf(fmaf(ra, m0.w, fmaf(rb, m1.w, hc.w)), 0.f));
}

// ---------------- generic 3xTF32 MMA GEMM (pre-split B) ----------------------
// 96x128 block, 8 warps (2x4), warp tile 48x32, BK=16.
__global__ void gemm_mma2_kernel(const float* __restrict__ A1, int lda1,
                                 const float* __restrict__ A2, int lda2, int split,
                                 const float2* __restrict__ Bhl, int ldk,
                                 const float* __restrict__ bias,
                                 float* __restrict__ Cm, int ldc,
                                 int Kdim, int doRelu) {
    __shared__ __align__(16) float As2[16][200];
    __shared__ __align__(16) float Bs2[16][264];
    int tid = threadIdx.x;
    int lane = tid & 31, wid = tid >> 5;
    int g = lane >> 2, tg = lane & 3;
    int warpM = wid >> 2, warpN = wid & 3;
    int n0 = blockIdx.x * 128, m0 = blockIdx.y * 96;

    float acc[3][4][4];
    #pragma unroll
    for (int mt = 0; mt < 3; mt++)
        #pragma unroll
        for (int nt = 0; nt < 4; nt++)
            #pragma unroll
            for (int q = 0; q < 4; q++) acc[mt][nt][q] = 0.f;

    for (int k0 = 0; k0 < Kdim; k0 += 16) {
        // A tile 96x16, split on the fly (small M -> cheap)
        for (int e = tid; e < 1536; e += 256) {
            int r = e >> 4, kk = e & 15;
            int kg = k0 + kk;
            float v = (kg < split) ? A1[(m0+r)*lda1 + kg]
                                   : A2[(m0+r)*lda2 + (kg - split)];
            ((float2*)&As2[kk][0])[r] = split_tf32(v);
        }
        // B tile 128x16: pure copy of pre-split pairs
        #pragma unroll
        for (int it = 0; it < 4; it++) {
            int u = tid + it*256;
            int n = u >> 3, q = u & 7;
            float4 w = *(const float4*)&Bhl[(n0 + n)*ldk + k0 + q*2];
            *(float2*)&Bs2[q*2+0][2*n] = make_float2(w.x, w.y);
            *(float2*)&Bs2[q*2+1][2*n] = make_float2(w.z, w.w);
        }
        __syncthreads();
        #pragma unroll
        for (int ks = 0; ks < 2; ks++) {
            int kb = ks * 8;
            float2 aF[3][4];
            #pragma unroll
            for (int mt = 0; mt < 3; mt++) {
                int rb = warpM*48 + mt*16;
                const float2* Ak0 = (const float2*)&As2[kb+tg][0];
                const float2* Ak4 = (const float2*)&As2[kb+tg+4][0];
                aF[mt][0] = Ak0[rb + g];
                aF[mt][1] = Ak0[rb + g + 8];
                aF[mt][2] = Ak4[rb + g];
                aF[mt][3] = Ak4[rb + g + 8];
            }
            float2 bF[4][2];
            #pragma unroll
            for (int nt = 0; nt < 4; nt++) {
                int nb = warpN*32 + nt*8;
                bF[nt][0] = ((const float2*)&Bs2[kb+tg][0])[nb + g];
                bF[nt][1] = ((const float2*)&Bs2[kb+tg+4][0])[nb + g];
            }
            #pragma unroll
            for (int mt = 0; mt < 3; mt++)
                #pragma unroll
                for (int nt = 0; nt < 4; nt++)
                    mma3(acc[mt][nt], aF[mt], bF[nt]);
        }
        __syncthreads();
    }
    #pragma unroll
    for (int mt = 0; mt < 3; mt++) {
        int r0 = m0 + warpM*48 + mt*16 + g;
        #pragma unroll
        for (int nt = 0; nt < 4; nt++) {
            int c0 = n0 + warpN*32 + nt*8 + 2*tg;
            float b0v = bias[c0], b1v = bias[c0+1];
            float v0 = acc[mt][nt][0] + b0v;
            float v1 = acc[mt][nt][1] + b1v;
            float v2 = acc[mt][nt][2] + b0v;
            float v3 = acc[mt][nt][3] + b1v;
            if (doRelu) {
                v0 = fmaxf(v0, 0.f); v1 = fmaxf(v1, 0.f);
                v2 = fmaxf(v2, 0.f); v3 = fmaxf(v3, 0.f);
            }
            *(float2*)&Cm[r0*ldc + c0]     = make_float2(v0, v1);
            *(float2*)&Cm[(r0+8)*ldc + c0] = make_float2(v2, v3);
        }
    }
}

// ---------------- pool kernel: pre-split A & B, 3xTF32 MMA + max over j ------
// grid (8, 384): m0 = blockIdx.y*96 covers 4 i's x 24 j's within one group.
__global__ void pool_mma2_kernel(const float* __restrict__ bp2) {
    __shared__ __align__(16) float As2[16][200];
    __shared__ __align__(16) float Bs2[16][264];
    __shared__ int red[4][128];
    int m0 = blockIdx.y * 96;
    int grp = m0 / 576;
    int i0  = (m0 % 576) / 24;
    int n0  = blockIdx.x * 128;
    int tid = threadIdx.x;
    int lane = tid & 31, wid = tid >> 5;
    int g = lane >> 2, tg = lane & 3;
    int warpM = wid >> 2, warpN = wid & 3;

    for (int l = tid; l < 512; l += 256) red[l >> 7][l & 127] = 0;

    float acc[3][4][4];
    #pragma unroll
    for (int mt = 0; mt < 3; mt++)
        #pragma unroll
        for (int nt = 0; nt < 4; nt++)
            #pragma unroll
            for (int q = 0; q < 4; q++) acc[mt][nt][q] = 0.f;

    for (int k0 = 0; k0 < 512; k0 += 16) {
        // A tile 96x16 copy (pre-split)
        #pragma unroll
        for (int it = 0; it < 3; it++) {
            int u = tid + it*256;
            int r = u >> 3, q = u & 7;
            float4 w = *(const float4*)&g_Ahl[(m0 + r)*512 + k0 + q*2];
            *(float2*)&As2[q*2+0][2*r] = make_float2(w.x, w.y);
            *(float2*)&As2[q*2+1][2*r] = make_float2(w.z, w.w);
        }
        // B tile 128x16 copy (pre-split Wp2)
        #pragma unroll
        for (int it = 0; it < 4; it++) {
            int u = tid + it*256;
            int n = u >> 3, q = u & 7;
            float4 w = *(const float4*)&g_Wp2hl[(n0 + n)*512 + k0 + q*2];
            *(float2*)&Bs2[q*2+0][2*n] = make_float2(w.x, w.y);
            *(float2*)&Bs2[q*2+1][2*n] = make_float2(w.z, w.w);
        }
        __syncthreads();
        #pragma unroll
        for (int ks = 0; ks < 2; ks++) {
            int kb = ks * 8;
            float2 aF[3][4];
            #pragma unroll
            for (int mt = 0; mt < 3; mt++) {
                int rb2 = warpM*48 + mt*16;
                const float2* Ak0 = (const float2*)&As2[kb+tg][0];
                const float2* Ak4 = (const float2*)&As2[kb+tg+4][0];
                aF[mt][0] = Ak0[rb2 + g];
                aF[mt][1] = Ak0[rb2 + g + 8];
                aF[mt][2] = Ak4[rb2 + g];
                aF[mt][3] = Ak4[rb2 + g + 8];
            }
            float2 bF[4][2];
            #pragma unroll
            for (int nt = 0; nt < 4; nt++) {
                int nb = warpN*32 + nt*8;
                bF[nt][0] = ((const float2*)&Bs2[kb+tg][0])[nb + g];
                bF[nt][1] = ((const float2*)&Bs2[kb+tg+4][0])[nb + g];
            }
            #pragma unroll
            for (int mt = 0; mt < 3; mt++)
                #pragma unroll
                for (int nt = 0; nt < 4; nt++)
                    mma3(acc[mt][nt], aF[mt], bF[nt]);
        }
        __syncthreads();
    }
    // epilogue: +bias, relu, max over 24 j-rows per i (relu>=0 -> int max ok)
    #pragma unroll
    for (int mt = 0; mt < 3; mt++) {
        int r = warpM*48 + mt*16 + g;
        int il0 = r / 24, il8 = (r + 8) / 24;
        #pragma unroll
        for (int nt = 0; nt < 4; nt++) {
            int n = warpN*32 + nt*8 + 2*tg;
            float b0v = bp2[n0 + n], b1v = bp2[n0 + n + 1];
            atomicMax(&red[il0][n],     __float_as_int(fmaxf(acc[mt][nt][0] + b0v, 0.f)));
            atomicMax(&red[il0][n + 1], __float_as_int(fmaxf(acc[mt][nt][1] + b1v, 0.f)));
            atomicMax(&red[il8][n],     __float_as_int(fmaxf(acc[mt][nt][2] + b0v, 0.f)));
            atomicMax(&red[il8][n + 1], __float_as_int(fmaxf(acc[mt][nt][3] + b1v, 0.f)));
        }
    }
    __syncthreads();
    for (int l = tid; l < 512; l += 256) {
        int il = l >> 7, n = l & 127;
        g_pool[(grp*24 + i0 + il)*1024 + n0 + n] = __int_as_float(red[il][n]);
    }
}

// ---------------- final hidden copy ------------------------------------------
__global__ void copyout_kernel(float* __restrict__ out) {
    int idx = blockIdx.x * blockDim.x + threadIdx.x;
    if (idx < BB*HD) out[SEQ*BB*2 + idx] = g_h[idx];
}

// ---------------- launch ------------------------------------------------------
static void* sym_addr(const void* sym) {
    void* p = nullptr;
    cudaGetSymbolAddress(&p, sym);
    return p;
}

extern "C" void kernel_launch(void* const* d_in, const int* in_sizes, int n_in,
                              void* d_out, int out_size) {
    const float* last_pos     = (const float*)d_in[0];
    const float* last_pos_rel = (const float*)d_in[1];
    const float* h0    = (const float*)d_in[2];
    const float* c0    = (const float*)d_in[3];
    const float* W_emb = (const float*)d_in[5];
    const float* b_emb = (const float*)d_in[6];
    const float* W_ih  = (const float*)d_in[7];
    const float* W_hh  = (const float*)d_in[8];
    const float* b_ih  = (const float*)d_in[9];
    const float* b_hh  = (const float*)d_in[10];
    const float* W_pos = (const float*)d_in[11];
    const float* b_pos = (const float*)d_in[12];
    const float* Wp_emb= (const float*)d_in[13];
    const float* bp_emb= (const float*)d_in[14];
    const float* Wp1   = (const float*)d_in[15];
    const float* bp1   = (const float*)d_in[16];
    const float* Wp2   = (const float*)d_in[17];
    const float* bp2   = (const float*)d_in[18];
    const float* Wm1   = (const float*)d_in[19];
    const float* bm1   = (const float*)d_in[20];
    const float* Wm2   = (const float*)d_in[21];
    const float* bm2   = (const float*)d_in[22];
    float* out = (float*)d_out;

    float*  p_hl     = (float*)sym_addr(g_hl);
    float*  p_h      = (float*)sym_addr(g_h);
    float*  p_hcon   = (float*)sym_addr(g_hcon);
    float*  p_pool   = (float*)sym_addr(g_pool);
    float*  p_mh     = (float*)sym_addr(g_mh);
    float*  p_biasc  = (float*)sym_addr(g_biasc);
    float2* p_Wp1hhl = (float2*)sym_addr(g_Wp1hhl);
    float2* p_Wm1hl  = (float2*)sym_addr(g_Wm1hl);
    float2* p_Wm2hl  = (float2*)sym_addr(g_Wm2hl);

    precompute_kernel<<<(512*128 + 255)/256, 256>>>(W_ih, W_hh, Wp1, Wp_emb, bp_emb, bp1);
    splitw_kernel<<<(1024*1152 + 255)/256, 256>>>(Wp1, Wp2, Wm1, Wm2);
    init_kernel<<<(BB*HD + 255)/256, 256>>>(h0, c0, last_pos, last_pos_rel, W_emb, b_emb);

    for (int s = 0; s < SEQ; s++) {
        lstm_kernel<<<BB/8, 256>>>(b_ih, b_hh);
        posdec_kernel<<<BB, 128>>>(W_pos, b_pos, W_emb, b_emb, out, s);
        // hcon = hl @ Wp1_h^T + biasc : [1536,512], K=128
        gemm_mma2_kernel<<<dim3(4, 16), 256>>>(
            p_hl, 128, p_hl, 128, 1 << 28,
            p_Wp1hhl, 128, p_biasc, p_hcon, 512, 128, 0);
        // build + split pool A matrix [36864,512]
        asplit_kernel<<<36864, 128>>>();
        // pool: [36864,512]@[512,1024]^T + bias + relu + max over j
        pool_mma2_kernel<<<dim3(8, 384), 256>>>(bp2);
        // mlp1: concat(hl, pool) [1536,1152] @ Wm1^T -> [1536,1024], relu
        gemm_mma2_kernel<<<dim3(8, 16), 256>>>(
            p_hl, 128, p_pool, 1024, 128,
            p_Wm1hl, 1152, bm1, p_mh, 1024, 1152, 1);
        // mlp2: [1536,1024] @ Wm2^T -> [1536,128], relu -> refreshed h
        gemm_mma2_kernel<<<dim3(1, 16), 256>>>(
            p_mh, 1024, p_mh, 1024, 1 << 28,
            p_Wm2hl, 1024, bm2, p_h, 128, 1024, 1);
    }
    copyout_kernel<<<(BB*HD + 255)/256, 256>>>(out);
}

// round 8
// speedup vs baseline: 1.5614x; 1.5614x over previous
#include <cuda_runtime.h>
#include <cuda_fp16.h>
#include <math.h>
#include <stdint.h>

#define BB 1536
#define SEQ 12

// ---------------- device scratch (no allocation) ------------------------------
__device__ float g_h[BB*128], g_c[BB*128], g_hl[BB*128];
__device__ float g_lp[BB*2], g_decin[BB*64];
__device__ float g_gates[BB*512], g_hcon[BB*512];
__device__ float g_pool[BB*1024], g_mh[BB*1024];
__device__ float g_M0[512], g_M1[512], g_biasc[512], g_biasg[512];
// fp16 hi/lo split operands: uint2{half2(hi_k,hi_k+1), half2(lo_k,lo_k+1)}
__device__ uint2 g_Xsp[BB*576];        // generic per-step A, [row][k2]
__device__ uint2 g_PAsp[36864*256];    // pool A, [row][k2]
__device__ uint2 g_Wgsp[96*512];       // weights, [k2][n]
__device__ uint2 g_W1sp[64*512];
__device__ uint2 g_Wp2sp[256*1024];
__device__ uint2 g_Wm1sp[576*1024];
__device__ uint2 g_Wm2sp[512*128];

// ---------------- helpers ------------------------------------------------------
__device__ __forceinline__ uint2 pack_split(float v0, float v1) {
    __half h0 = __float2half_rn(v0);
    __half h1 = __float2half_rn(v1);
    __half l0 = __float2half_rn(v0 - __half2float(h0));
    __half l1 = __float2half_rn(v1 - __half2float(h1));
    __half2 hh = __halves2half2(h0, h1);
    __half2 ll = __halves2half2(l0, l1);
    uint2 r;
    r.x = *reinterpret_cast<unsigned*>(&hh);
    r.y = *reinterpret_cast<unsigned*>(&ll);
    return r;
}

__device__ __forceinline__ void hmma(float* c, unsigned a0, unsigned a1, unsigned a2,
                                     unsigned a3, unsigned b0, unsigned b1) {
    asm("mma.sync.aligned.m16n8k16.row.col.f32.f16.f16.f32 "
        "{%0,%1,%2,%3},{%4,%5,%6,%7},{%8,%9},{%0,%1,%2,%3};"
        : "+f"(c[0]), "+f"(c[1]), "+f"(c[2]), "+f"(c[3])
        : "r"(a0), "r"(a1), "r"(a2), "r"(a3), "r"(b0), "r"(b1));
}

// ---------------- fp16x3 MMA GEMM: C = act(A @ B^T + bias) --------------------
// block 96x128, 8 warps (2x4), warp tile 48x32 (3x4 m16n8k16 tiles), BK=32.
// poolMode: relu + max over 24-row buckets (m-tiles are 24-aligned).
__global__ __launch_bounds__(256)
void hgemm_kernel(const uint2* __restrict__ Asp, int K2,
                  const uint2* __restrict__ Bsp, int Nfull,
                  const float* __restrict__ bias,
                  float* __restrict__ C, int ldc,
                  int doRelu, int poolMode) {
    __shared__ uint2 As[16][100];   // [k2][row], stride 100 (≡4 mod 16: conflict-free frags)
    __shared__ uint2 Bs[16][132];   // [k2][col], stride 132
    __shared__ int red[4][128];
    int tid = threadIdx.x;
    int lane = tid & 31, wid = tid >> 5;
    int g = lane >> 2, tg = lane & 3;
    int warpM = wid >> 2, warpN = wid & 3;
    int n0 = blockIdx.x * 128, m0 = blockIdx.y * 96;

    if (poolMode) {
        for (int l = tid; l < 512; l += 256) red[l >> 7][l & 127] = 0;
    }

    float acc[3][4][4];
    #pragma unroll
    for (int mt = 0; mt < 3; mt++)
        #pragma unroll
        for (int nt = 0; nt < 4; nt++)
            #pragma unroll
            for (int q = 0; q < 4; q++) acc[mt][nt][q] = 0.f;

    for (int k0 = 0; k0 < K2; k0 += 16) {
        for (int e = tid; e < 1536; e += 256) {
            int r = e >> 4, q = e & 15;
            As[q][r] = Asp[(m0 + r) * K2 + k0 + q];
        }
        for (int e = tid; e < 2048; e += 256) {
            int q = e >> 7, n = e & 127;
            Bs[q][n] = Bsp[(k0 + q) * Nfull + n0 + n];
        }
        __syncthreads();
        #pragma unroll
        for (int ks = 0; ks < 2; ks++) {
            int kb = ks * 8;
            unsigned ahi[3][4], alo[3][4];
            #pragma unroll
            for (int mt = 0; mt < 3; mt++) {
                int rb = warpM * 48 + mt * 16;
                uint2 x0 = As[kb + tg][rb + g];
                uint2 x1 = As[kb + tg][rb + g + 8];
                uint2 x2 = As[kb + tg + 4][rb + g];
                uint2 x3 = As[kb + tg + 4][rb + g + 8];
                ahi[mt][0] = x0.x; ahi[mt][1] = x1.x; ahi[mt][2] = x2.x; ahi[mt][3] = x3.x;
                alo[mt][0] = x0.y; alo[mt][1] = x1.y; alo[mt][2] = x2.y; alo[mt][3] = x3.y;
            }
            unsigned bhi[4][2], blo[4][2];
            #pragma unroll
            for (int nt = 0; nt < 4; nt++) {
                int nb = warpN * 32 + nt * 8;
                uint2 y0 = Bs[kb + tg][nb + g];
                uint2 y1 = Bs[kb + tg + 4][nb + g];
                bhi[nt][0] = y0.x; bhi[nt][1] = y1.x;
                blo[nt][0] = y0.y; blo[nt][1] = y1.y;
            }
            #pragma unroll
            for (int mt = 0; mt < 3; mt++)
                #pragma unroll
                for (int nt = 0; nt < 4; nt++) {
                    hmma(acc[mt][nt], ahi[mt][0], ahi[mt][1], ahi[mt][2], ahi[mt][3],
                         bhi[nt][0], bhi[nt][1]);
                    hmma(acc[mt][nt], ahi[mt][0], ahi[mt][1], ahi[mt][2], ahi[mt][3],
                         blo[nt][0], blo[nt][1]);
                    hmma(acc[mt][nt], alo[mt][0], alo[mt][1], alo[mt][2], alo[mt][3],
                         bhi[nt][0], bhi[nt][1]);
                }
        }
        __syncthreads();
    }

    if (!poolMode) {
        #pragma unroll
        for (int mt = 0; mt < 3; mt++) {
            int r0 = m0 + warpM * 48 + mt * 16 + g;
            #pragma unroll
            for (int nt = 0; nt < 4; nt++) {
                int c0 = n0 + warpN * 32 + nt * 8 + 2 * tg;
                float b0v = bias[c0], b1v = bias[c0 + 1];
                float v0 = acc[mt][nt][0] + b0v;
                float v1 = acc[mt][nt][1] + b1v;
                float v2 = acc[mt][nt][2] + b0v;
                float v3 = acc[mt][nt][3] + b1v;
                if (doRelu) {
                    v0 = fmaxf(v0, 0.f); v1 = fmaxf(v1, 0.f);
                    v2 = fmaxf(v2, 0.f); v3 = fmaxf(v3, 0.f);
                }
                *(float2*)&C[r0 * ldc + c0]       = make_float2(v0, v1);
                *(float2*)&C[(r0 + 8) * ldc + c0] = make_float2(v2, v3);
            }
        }
    } else {
        // relu(+bias) then max over j-rows; 96-row tile = exactly 4 buckets of 24
        #pragma unroll
        for (int mt = 0; mt < 3; mt++) {
            int r = warpM * 48 + mt * 16 + g;
            int il0 = r / 24, il8 = (r + 8) / 24;
            #pragma unroll
            for (int nt = 0; nt < 4; nt++) {
                int n = warpN * 32 + nt * 8 + 2 * tg;
                float b0v = bias[n0 + n], b1v = bias[n0 + n + 1];
                atomicMax(&red[il0][n],     __float_as_int(fmaxf(acc[mt][nt][0] + b0v, 0.f)));
                atomicMax(&red[il0][n + 1], __float_as_int(fmaxf(acc[mt][nt][1] + b1v, 0.f)));
                atomicMax(&red[il8][n],     __float_as_int(fmaxf(acc[mt][nt][2] + b0v, 0.f)));
                atomicMax(&red[il8][n + 1], __float_as_int(fmaxf(acc[mt][nt][3] + b1v, 0.f)));
            }
        }
        __syncthreads();
        int bucket0 = m0 / 24;
        for (int l = tid; l < 512; l += 256) {
            int il = l >> 7, n = l & 127;
            C[(bucket0 + il) * ldc + n0 + n] = __int_as_float(red[il][n]);
        }
    }
}

// ---------------- precompute / splits ------------------------------------------
__global__ void precompute_kernel(const float* __restrict__ Wp1,
                                  const float* __restrict__ Wp_emb,
                                  const float* __restrict__ bp_emb,
                                  const float* __restrict__ bp1,
                                  const float* __restrict__ bih,
                                  const float* __restrict__ bhh) {
    int idx = blockIdx.x * blockDim.x + threadIdx.x;
    if (idx < 512) {
        float m0 = 0.f, m1 = 0.f, bc = 0.f;
        for (int e = 0; e < 64; e++) {
            float w = Wp1[idx*192 + e];
            m0 += w * Wp_emb[e*2 + 0];
            m1 += w * Wp_emb[e*2 + 1];
            bc += w * bp_emb[e];
        }
        g_M0[idx] = m0; g_M1[idx] = m1;
        g_biasc[idx] = bp1[idx] + bc;
        g_biasg[idx] = bih[idx] + bhh[idx];
    }
}

__global__ void splitw_kernel(const float* __restrict__ Wih, const float* __restrict__ Whh,
                              const float* __restrict__ Wp1, const float* __restrict__ Wp2,
                              const float* __restrict__ Wm1, const float* __restrict__ Wm2) {
    int idx = blockIdx.x * blockDim.x + threadIdx.x;
    if (idx < 96*512) {           // gates W: [n=512][k=192 concat]
        int k2 = idx / 512, n = idx % 512, k = 2*k2;
        float v0 = (k < 64) ? Wih[n*64 + k]     : Whh[n*128 + (k - 64)];
        float v1 = (k+1 < 64) ? Wih[n*64 + k+1] : Whh[n*128 + (k+1 - 64)];
        g_Wgsp[idx] = pack_split(v0, v1);
    }
    if (idx < 64*512) {           // W1 = Wp1[:,64:192]
        int k2 = idx / 512, n = idx % 512, k = 2*k2;
        g_W1sp[idx] = pack_split(Wp1[n*192 + 64 + k], Wp1[n*192 + 64 + k + 1]);
    }
    if (idx < 256*1024) {         // Wp2 [1024][512]
        int k2 = idx >> 10, n = idx & 1023, k = 2*k2;
        g_Wp2sp[idx] = pack_split(Wp2[n*512 + k], Wp2[n*512 + k + 1]);
    }
    if (idx < 576*1024) {         // Wm1 [1024][1152]
        int k2 = idx >> 10, n = idx & 1023, k = 2*k2;
        g_Wm1sp[idx] = pack_split(Wm1[n*1152 + k], Wm1[n*1152 + k + 1]);
    }
    if (idx < 512*128) {          // Wm2 [128][1024]
        int k2 = idx >> 7, n = idx & 127, k = 2*k2;
        g_Wm2sp[idx] = pack_split(Wm2[n*1024 + k], Wm2[n*1024 + k + 1]);
    }
}

__global__ void init_kernel(const float* __restrict__ h0, const float* __restrict__ c0,
                            const float* __restrict__ lp, const float* __restrict__ lpr,
                            const float* __restrict__ Wemb, const float* __restrict__ bemb) {
    int idx = blockIdx.x * blockDim.x + threadIdx.x;
    if (idx < BB*128) { g_h[idx] = h0[idx]; g_c[idx] = c0[idx]; }
    if (idx < BB*2)   { g_lp[idx] = lp[idx]; }
    if (idx < BB*64) {
        int b = idx >> 6, e = idx & 63;
        g_decin[idx] = lpr[b*2]*Wemb[e*2] + lpr[b*2+1]*Wemb[e*2+1] + bemb[e];
    }
}

// generic A split (concat of two sources), output [row][k2]
__global__ void splitA_kernel(const float* __restrict__ A1, int w1,
                              const float* __restrict__ A2, int w2,
                              int K2, int total) {
    for (int idx = blockIdx.x * blockDim.x + threadIdx.x; idx < total;
         idx += gridDim.x * blockDim.x) {
        int r = idx / K2, k2 = idx - r * K2, k = 2 * k2;
        float2 v = (k < w1) ? *(const float2*)&A1[r*w1 + k]
                            : *(const float2*)&A2[r*w2 + (k - w1)];
        g_Xsp[idx] = pack_split(v.x, v.y);
    }
}

// pool A build + split: row = g*576 + i*24 + j, fused layer-1, [row][k2]
__global__ void asplit_kernel() {
    int row = blockIdx.x;
    int grp = row / 576;
    int rem = row - grp*576;
    int i = rem / 24, j = rem - (rem/24)*24;
    int t = threadIdx.x;
    float pix = g_lp[(grp*24 + i)*2 + 0];
    float piy = g_lp[(grp*24 + i)*2 + 1];
    float pjx = g_lp[(grp*24 + j)*2 + 0];
    float pjy = g_lp[(grp*24 + j)*2 + 1];
    float dx = pjx - pix, dy = pjy - piy;
    float inv = 1.f / fmaxf(sqrtf(dx*dx + dy*dy), 1e-12f);
    float ra = dx * inv, rb = dy * inv;
    int k = t * 4;
    const float4 hc = *(const float4*)&g_hcon[(grp*24 + j)*512 + k];
    const float4 m0 = *(const float4*)&g_M0[k];
    const float4 m1 = *(const float4*)&g_M1[k];
    float v0 = fmaxf(fmaf(ra, m0.x, fmaf(rb, m1.x, hc.x)), 0.f);
    float v1 = fmaxf(fmaf(ra, m0.y, fmaf(rb, m1.y, hc.y)), 0.f);
    float v2 = fmaxf(fmaf(ra, m0.z, fmaf(rb, m1.z, hc.z)), 0.f);
    float v3 = fmaxf(fmaf(ra, m0.w, fmaf(rb, m1.w, hc.w)), 0.f);
    uint2 u0 = pack_split(v0, v1);
    uint2 u1 = pack_split(v2, v3);
    *(uint4*)&g_PAsp[row*256 + 2*t] = make_uint4(u0.x, u0.y, u1.x, u1.y);
}

// LSTM activations from precomputed gates
__global__ void act_kernel() {
    int idx = blockIdx.x * blockDim.x + threadIdx.x;
    if (idx >= BB*128) return;
    int r = idx >> 7, u = idx & 127;
    float gi = g_gates[r*512 + u];
    float gf = g_gates[r*512 + u + 128];
    float gg = g_gates[r*512 + u + 256];
    float go = g_gates[r*512 + u + 384];
    float si = 1.f / (1.f + __expf(-gi));
    float sf = 1.f / (1.f + __expf(-gf));
    float so = 1.f / (1.f + __expf(-go));
    float cc = sf * g_c[idx] + si * tanhf(gg);
    g_c[idx]  = cc;
    g_hl[idx] = so * tanhf(cc);
}

__global__ void posdec_kernel(const float* __restrict__ Wpos, const float* __restrict__ bpos,
                              const float* __restrict__ Wemb, const float* __restrict__ bemb,
                              float* __restrict__ rels_out, int step) {
    int b = blockIdx.x;
    int t = threadIdx.x;
    __shared__ float hr[128];
    __shared__ float sr[2];
    hr[t] = g_hl[b*128 + t];
    __syncthreads();
    int w = t >> 5, lane = t & 31;
    if (w < 2) {
        float part = 0.f;
        for (int k = lane; k < 128; k += 32) part += hr[k] * Wpos[w*128 + k];
        #pragma unroll
        for (int off = 16; off; off >>= 1) part += __shfl_down_sync(0xffffffffu, part, off);
        if (lane == 0) sr[w] = part + bpos[w];
    }
    __syncthreads();
    float ra = sr[0], rb = sr[1];
    if (t < 64) g_decin[b*64 + t] = ra*Wemb[t*2] + rb*Wemb[t*2+1] + bemb[t];
    if (t == 0) {
        rels_out[(step*BB + b)*2 + 0] = ra;
        rels_out[(step*BB + b)*2 + 1] = rb;
        g_lp[b*2 + 0] += ra;
        g_lp[b*2 + 1] += rb;
    }
}

__global__ void copyout_kernel(float* __restrict__ out) {
    int idx = blockIdx.x * blockDim.x + threadIdx.x;
    if (idx < BB*128) out[SEQ*BB*2 + idx] = g_h[idx];
}

// ---------------- launch -------------------------------------------------------
static void* sym_addr(const void* s) { void* p = nullptr; cudaGetSymbolAddress(&p, s); return p; }

extern "C" void kernel_launch(void* const* d_in, const int* in_sizes, int n_in,
                              void* d_out, int out_size) {
    const float* last_pos     = (const float*)d_in[0];
    const float* last_pos_rel = (const float*)d_in[1];
    const float* h0    = (const float*)d_in[2];
    const float* c0    = (const float*)d_in[3];
    const float* W_emb = (const float*)d_in[5];
    const float* b_emb = (const float*)d_in[6];
    const float* W_ih  = (const float*)d_in[7];
    const float* W_hh  = (const float*)d_in[8];
    const float* b_ih  = (const float*)d_in[9];
    const float* b_hh  = (const float*)d_in[10];
    const float* W_pos = (const float*)d_in[11];
    const float* b_pos = (const float*)d_in[12];
    const float* Wp_emb= (const float*)d_in[13];
    const float* bp_emb= (const float*)d_in[14];
    const float* Wp1   = (const float*)d_in[15];
    const float* bp1   = (const float*)d_in[16];
    const float* Wp2   = (const float*)d_in[17];
    const float* bp2   = (const float*)d_in[18];
    const float* Wm1   = (const float*)d_in[19];
    const float* bm1   = (const float*)d_in[20];
    const float* Wm2   = (const float*)d_in[21];
    const float* bm2   = (const float*)d_in[22];
    float* out = (float*)d_out;

    float* p_decin = (float*)sym_addr(g_decin);
    float* p_h     = (float*)sym_addr(g_h);
    float* p_hl    = (float*)sym_addr(g_hl);
    float* p_gates = (float*)sym_addr(g_gates);
    float* p_hcon  = (float*)sym_addr(g_hcon);
    float* p_pool  = (float*)sym_addr(g_pool);
    float* p_mh    = (float*)sym_addr(g_mh);
    float* p_biasc = (float*)sym_addr(g_biasc);
    float* p_biasg = (float*)sym_addr(g_biasg);
    uint2* p_Xsp   = (uint2*)sym_addr(g_Xsp);
    uint2* p_PAsp  = (uint2*)sym_addr(g_PAsp);
    uint2* p_Wgsp  = (uint2*)sym_addr(g_Wgsp);
    uint2* p_W1sp  = (uint2*)sym_addr(g_W1sp);
    uint2* p_Wp2sp = (uint2*)sym_addr(g_Wp2sp);
    uint2* p_Wm1sp = (uint2*)sym_addr(g_Wm1sp);
    uint2* p_Wm2sp = (uint2*)sym_addr(g_Wm2sp);

    precompute_kernel<<<2, 256>>>(Wp1, Wp_emb, bp_emb, bp1, b_ih, b_hh);
    splitw_kernel<<<(576*1024 + 255)/256, 256>>>(W_ih, W_hh, Wp1, Wp2, Wm1, Wm2);
    init_kernel<<<(BB*128 + 255)/256, 256>>>(h0, c0, last_pos, last_pos_rel, W_emb, b_emb);

    for (int s = 0; s < SEQ; s++) {
        // LSTM gates = [decin | h] @ Wg^T + (bih+bhh) : [1536,512], K=192
        splitA_kernel<<<576, 256>>>(p_decin, 64, p_h, 128, 96, BB*96);
        hgemm_kernel<<<dim3(4, 16), 256>>>(p_Xsp, 96, p_Wgsp, 512, p_biasg, p_gates, 512, 0, 0);
        act_kernel<<<(BB*128 + 255)/256, 256>>>();
        posdec_kernel<<<BB, 128>>>(W_pos, b_pos, W_emb, b_emb, out, s);
        // hcon = hl @ Wp1_h^T + biasc : [1536,512], K=128
        splitA_kernel<<<384, 256>>>(p_hl, 128, p_hl, 128, 64, BB*64);
        hgemm_kernel<<<dim3(4, 16), 256>>>(p_Xsp, 64, p_W1sp, 512, p_biasc, p_hcon, 512, 0, 0);
        // pool: build split A, then [36864,512]@[512,1024]^T + relu + max over j
        asplit_kernel<<<36864, 128>>>();
        hgemm_kernel<<<dim3(8, 384), 256>>>(p_PAsp, 256, p_Wp2sp, 1024, bp2, p_pool, 1024, 1, 1);
        // mlp1: [hl | pool] @ Wm1^T + bm1, relu : [1536,1024], K=1152
        splitA_kernel<<<3456, 256>>>(p_hl, 128, p_pool, 1024, 576, BB*576);
        hgemm_kernel<<<dim3(8, 16), 256>>>(p_Xsp, 576, p_Wm1sp, 1024, bm1, p_mh, 1024, 1, 0);
        // mlp2: mh @ Wm2^T + bm2, relu -> refreshed h : [1536,128], K=1024
        splitA_kernel<<<3072, 256>>>(p_mh, 1024, p_mh, 1024, 512, BB*512);
        hgemm_kernel<<<dim3(1, 16), 256>>>(p_Xsp, 512, p_Wm2sp, 128, bm2, p_h, 128, 1, 0);
    }
    copyout_kernel<<<(BB*128 + 255)/256, 256>>>(out);
}

// round 9
// speedup vs baseline: 2.8843x; 1.8473x over previous
#include <cuda_runtime.h>
#include <cuda_fp16.h>
#include <math.h>
#include <stdint.h>

#define BB 1536
#define SEQ 12

// ---------------- device scratch (no allocation) ------------------------------
__device__ float g_h[BB*128], g_c[BB*128], g_hl[BB*128];
__device__ float g_lp[BB*2];
__device__ float g_part[4*BB*512];                 // split-K partial sums
__device__ float g_M0[512], g_M1[512], g_biasc[512], g_biasg[512];
// fp16 hi/lo split operands: uint2{half2(hi), half2(lo)} per k-pair
__device__ uint2 g_Xg[BB*96];          // gates input split: [row][k2] (decin 0..31 | h 32..95)
__device__ uint2 g_Xm1[BB*576];        // mlp1 input split: hl 0..63 | pool 64..575
__device__ uint2 g_Ysp[BB*512];        // mlp2 input split (mlp1 output)
__device__ uint2 g_PAsp[36864*256];    // pool A split, [row][k2]
__device__ uint2 g_Wgsp[96*512];       // weights, [k2][n]
__device__ uint2 g_W1sp[64*512];
__device__ uint2 g_Wp2sp[256*1024];
__device__ uint2 g_Wm1sp[576*1024];
__device__ uint2 g_Wm2sp[512*128];

// ---------------- helpers ------------------------------------------------------
__device__ __forceinline__ uint32_t smem_u32(const void* p) {
    uint32_t a;
    asm("{ .reg .u64 t; cvta.to.shared.u64 t, %1; cvt.u32.u64 %0, t; }" : "=r"(a) : "l"(p));
    return a;
}
__device__ __forceinline__ uint2 pack_split(float v0, float v1) {
    __half h0 = __float2half_rn(v0);
    __half h1 = __float2half_rn(v1);
    __half l0 = __float2half_rn(v0 - __half2float(h0));
    __half l1 = __float2half_rn(v1 - __half2float(h1));
    __half2 hh = __halves2half2(h0, h1);
    __half2 ll = __halves2half2(l0, l1);
    uint2 r;
    r.x = *reinterpret_cast<unsigned*>(&hh);
    r.y = *reinterpret_cast<unsigned*>(&ll);
    return r;
}
__device__ __forceinline__ void hmma(float* c, unsigned a0, unsigned a1, unsigned a2,
                                     unsigned a3, unsigned b0, unsigned b1) {
    asm("mma.sync.aligned.m16n8k16.row.col.f32.f16.f16.f32 "
        "{%0,%1,%2,%3},{%4,%5,%6,%7},{%8,%9},{%0,%1,%2,%3};"
        : "+f"(c[0]), "+f"(c[1]), "+f"(c[2]), "+f"(c[3])
        : "r"(a0), "r"(a1), "r"(a2), "r"(a3), "r"(b0), "r"(b1));
}

// ---------------- fp16x3 MMA GEMM, cp.async double-buffered -------------------
// block 96x128, 8 warps (2x4), warp 48x32 (3x4 m16n8k16 tiles), stage BK=32.
// mode 2: pool (bias+relu+max over 24-row buckets, split-packed out to g_Xm1)
// mode 3: bias+relu, split-packed store (uint2) for the next GEMM
// mode 4: raw partial store (split-K slice z at C + z*Mfull*ldc), no bias
__global__ __launch_bounds__(256)
void hgemm_kernel(const uint2* __restrict__ Asp, int Astride, int kLen,
                  const uint2* __restrict__ Bsp, int Nfull,
                  const float* __restrict__ bias,
                  void* __restrict__ Cout, int ldc, int mode) {
    extern __shared__ uint2 smbuf[];                 // As[2][16][100] | Bs[2][16][132] | red
    uint2* AsBuf = smbuf;
    uint2* BsBuf = smbuf + 3200;
    int*   red   = (int*)(smbuf + 3200 + 4224);
    uint32_t sb = smem_u32(smbuf);

    int tid = threadIdx.x;
    int lane = tid & 31, wid = tid >> 5;
    int g = lane >> 2, tg = lane & 3;
    int warpM = wid >> 2, warpN = wid & 3;
    int n0 = blockIdx.x * 128, m0 = blockIdx.y * 96;
    int z = blockIdx.z;
    int kOff = z * kLen;
    int S = kLen >> 4;                               // stages of 16 k2 (= K 32)

    if (mode == 2) {
        for (int l = tid; l < 512; l += 256) red[l] = 0;
    }

    auto issue = [&](int buf, int k0g) {
        uint32_t abase = sb + (uint32_t)buf * 1600u * 8u;
        int e = tid;
        #pragma unroll
        for (int it = 0; it < 6; it++, e += 256) {
            int r = e >> 4, q = e & 15;
            const void* src = Asp + (size_t)(m0 + r) * Astride + k0g + q;
            uint32_t dst = abase + (uint32_t)(q * 100 + r) * 8u;
            asm volatile("cp.async.ca.shared.global [%0], [%1], 8;" :: "r"(dst), "l"(src));
        }
        uint32_t bbase = sb + (3200u + (uint32_t)buf * 2112u) * 8u;
        e = tid;
        #pragma unroll
        for (int it = 0; it < 8; it++, e += 256) {
            int q = e >> 7, n = e & 127;
            const void* src = Bsp + (size_t)(k0g + q) * Nfull + n0 + n;
            uint32_t dst = bbase + (uint32_t)(q * 132 + n) * 8u;
            asm volatile("cp.async.ca.shared.global [%0], [%1], 8;" :: "r"(dst), "l"(src));
        }
        asm volatile("cp.async.commit_group;");
    };

    float acc[3][4][4];
    #pragma unroll
    for (int mt = 0; mt < 3; mt++)
        #pragma unroll
        for (int nt = 0; nt < 4; nt++)
            #pragma unroll
            for (int q = 0; q < 4; q++) acc[mt][nt][q] = 0.f;

    issue(0, kOff);
    for (int s = 0; s < S; s++) {
        if (s + 1 < S) {
            issue((s + 1) & 1, kOff + ((s + 1) << 4));
            asm volatile("cp.async.wait_group 1;");
        } else {
            asm volatile("cp.async.wait_group 0;");
        }
        __syncthreads();
        const uint2* As = AsBuf + (s & 1) * 1600;
        const uint2* Bs = BsBuf + (s & 1) * 2112;
        #pragma unroll
        for (int ks = 0; ks < 2; ks++) {
            int kb = ks * 8;
            unsigned ahi[3][4], alo[3][4];
            #pragma unroll
            for (int mt = 0; mt < 3; mt++) {
                int rb = warpM * 48 + mt * 16;
                uint2 x0 = As[(kb + tg) * 100 + rb + g];
                uint2 x1 = As[(kb + tg) * 100 + rb + g + 8];
                uint2 x2 = As[(kb + tg + 4) * 100 + rb + g];
                uint2 x3 = As[(kb + tg + 4) * 100 + rb + g + 8];
                ahi[mt][0] = x0.x; ahi[mt][1] = x1.x; ahi[mt][2] = x2.x; ahi[mt][3] = x3.x;
                alo[mt][0] = x0.y; alo[mt][1] = x1.y; alo[mt][2] = x2.y; alo[mt][3] = x3.y;
            }
            unsigned bhi[4][2], blo[4][2];
            #pragma unroll
            for (int nt = 0; nt < 4; nt++) {
                int nb = warpN * 32 + nt * 8;
                uint2 y0 = Bs[(kb + tg) * 132 + nb + g];
                uint2 y1 = Bs[(kb + tg + 4) * 132 + nb + g];
                bhi[nt][0] = y0.x; bhi[nt][1] = y1.x;
                blo[nt][0] = y0.y; blo[nt][1] = y1.y;
            }
            #pragma unroll
            for (int mt = 0; mt < 3; mt++)
                #pragma unroll
                for (int nt = 0; nt < 4; nt++) {
                    hmma(acc[mt][nt], ahi[mt][0], ahi[mt][1], ahi[mt][2], ahi[mt][3],
                         bhi[nt][0], bhi[nt][1]);
                    hmma(acc[mt][nt], ahi[mt][0], ahi[mt][1], ahi[mt][2], ahi[mt][3],
                         blo[nt][0], blo[nt][1]);
                    hmma(acc[mt][nt], alo[mt][0], alo[mt][1], alo[mt][2], alo[mt][3],
                         bhi[nt][0], bhi[nt][1]);
                }
        }
        __syncthreads();
    }

    if (mode == 4) {
        float* C = (float*)Cout + (size_t)z * (size_t)(gridDim.y * 96) * ldc;
        #pragma unroll
        for (int mt = 0; mt < 3; mt++) {
            int r0 = m0 + warpM * 48 + mt * 16 + g;
            #pragma unroll
            for (int nt = 0; nt < 4; nt++) {
                int c0 = n0 + warpN * 32 + nt * 8 + 2 * tg;
                *(float2*)&C[(size_t)r0 * ldc + c0]       = make_float2(acc[mt][nt][0], acc[mt][nt][1]);
                *(float2*)&C[(size_t)(r0 + 8) * ldc + c0] = make_float2(acc[mt][nt][2], acc[mt][nt][3]);
            }
        }
    } else if (mode == 3) {
        uint2* Y = (uint2*)Cout;
        int K2o = ldc >> 1;
        #pragma unroll
        for (int mt = 0; mt < 3; mt++) {
            int r0 = m0 + warpM * 48 + mt * 16 + g;
            #pragma unroll
            for (int nt = 0; nt < 4; nt++) {
                int c0 = n0 + warpN * 32 + nt * 8 + 2 * tg;
                float b0v = bias[c0], b1v = bias[c0 + 1];
                float v0 = fmaxf(acc[mt][nt][0] + b0v, 0.f);
                float v1 = fmaxf(acc[mt][nt][1] + b1v, 0.f);
                float v2 = fmaxf(acc[mt][nt][2] + b0v, 0.f);
                float v3 = fmaxf(acc[mt][nt][3] + b1v, 0.f);
                Y[(size_t)r0 * K2o + (c0 >> 1)]       = pack_split(v0, v1);
                Y[(size_t)(r0 + 8) * K2o + (c0 >> 1)] = pack_split(v2, v3);
            }
        }
    } else {  // mode 2: pool
        #pragma unroll
        for (int mt = 0; mt < 3; mt++) {
            int r = warpM * 48 + mt * 16 + g;
            int il0 = r / 24, il8 = (r + 8) / 24;
            #pragma unroll
            for (int nt = 0; nt < 4; nt++) {
                int n = warpN * 32 + nt * 8 + 2 * tg;
                float b0v = bias[n0 + n], b1v = bias[n0 + n + 1];
                atomicMax(&red[il0 * 128 + n],     __float_as_int(fmaxf(acc[mt][nt][0] + b0v, 0.f)));
                atomicMax(&red[il0 * 128 + n + 1], __float_as_int(fmaxf(acc[mt][nt][1] + b1v, 0.f)));
                atomicMax(&red[il8 * 128 + n],     __float_as_int(fmaxf(acc[mt][nt][2] + b0v, 0.f)));
                atomicMax(&red[il8 * 128 + n + 1], __float_as_int(fmaxf(acc[mt][nt][3] + b1v, 0.f)));
            }
        }
        __syncthreads();
        int bucket0 = blockIdx.y * 4;
        int il = tid >> 6, n2 = tid & 63;
        float v0 = __int_as_float(red[il * 128 + 2 * n2]);
        float v1 = __int_as_float(red[il * 128 + 2 * n2 + 1]);
        ((uint2*)Cout)[(size_t)(bucket0 + il) * 576 + 64 + (n0 >> 1) + n2] = pack_split(v0, v1);
    }
}

// ---------------- precompute / weight splits ----------------------------------
__global__ void precompute_kernel(const float* __restrict__ Wp1,
                                  const float* __restrict__ Wp_emb,
                                  const float* __restrict__ bp_emb,
                                  const float* __restrict__ bp1,
                                  const float* __restrict__ bih,
                                  const float* __restrict__ bhh) {
    int idx = blockIdx.x * blockDim.x + threadIdx.x;
    if (idx < 512) {
        float m0 = 0.f, m1 = 0.f, bc = 0.f;
        for (int e = 0; e < 64; e++) {
            float w = Wp1[idx*192 + e];
            m0 += w * Wp_emb[e*2 + 0];
            m1 += w * Wp_emb[e*2 + 1];
            bc += w * bp_emb[e];
        }
        g_M0[idx] = m0; g_M1[idx] = m1;
        g_biasc[idx] = bp1[idx] + bc;
        g_biasg[idx] = bih[idx] + bhh[idx];
    }
}

__global__ void splitw_kernel(const float* __restrict__ Wih, const float* __restrict__ Whh,
                              const float* __restrict__ Wp1, const float* __restrict__ Wp2,
                              const float* __restrict__ Wm1, const float* __restrict__ Wm2) {
    int idx = blockIdx.x * blockDim.x + threadIdx.x;
    if (idx < 96*512) {
        int k2 = idx / 512, n = idx % 512, k = 2*k2;
        float v0 = (k < 64) ? Wih[n*64 + k]     : Whh[n*128 + (k - 64)];
        float v1 = (k+1 < 64) ? Wih[n*64 + k+1] : Whh[n*128 + (k+1 - 64)];
        g_Wgsp[idx] = pack_split(v0, v1);
    }
    if (idx < 64*512) {
        int k2 = idx / 512, n = idx % 512, k = 2*k2;
        g_W1sp[idx] = pack_split(Wp1[n*192 + 64 + k], Wp1[n*192 + 64 + k + 1]);
    }
    if (idx < 256*1024) {
        int k2 = idx >> 10, n = idx & 1023, k = 2*k2;
        g_Wp2sp[idx] = pack_split(Wp2[n*512 + k], Wp2[n*512 + k + 1]);
    }
    if (idx < 576*1024) {
        int k2 = idx >> 10, n = idx & 1023, k = 2*k2;
        g_Wm1sp[idx] = pack_split(Wm1[n*1152 + k], Wm1[n*1152 + k + 1]);
    }
    if (idx < 512*128) {
        int k2 = idx >> 7, n = idx & 127, k = 2*k2;
        g_Wm2sp[idx] = pack_split(Wm2[n*1024 + k], Wm2[n*1024 + k + 1]);
    }
}

__global__ void init_kernel(const float* __restrict__ h0, const float* __restrict__ c0,
                            const float* __restrict__ lp, const float* __restrict__ lpr,
                            const float* __restrict__ Wemb, const float* __restrict__ bemb) {
    int idx = blockIdx.x * blockDim.x + threadIdx.x;
    if (idx < BB*64) {
        int r = idx >> 6, u2 = idx & 63, u = 2*u2;
        float hv0 = h0[r*128 + u], hv1 = h0[r*128 + u + 1];
        *(float2*)&g_h[r*128 + u] = make_float2(hv0, hv1);
        *(float2*)&g_c[r*128 + u] = make_float2(c0[r*128 + u], c0[r*128 + u + 1]);
        g_Xg[r*96 + 32 + u2] = pack_split(hv0, hv1);
    }
    if (idx < BB*32) {
        int b = idx >> 5, t = idx & 31;
        int e0 = 2*t, e1 = 2*t + 1;
        float ra = lpr[b*2], rb = lpr[b*2 + 1];
        float v0 = ra*Wemb[e0*2] + rb*Wemb[e0*2+1] + bemb[e0];
        float v1 = ra*Wemb[e1*2] + rb*Wemb[e1*2+1] + bemb[e1];
        g_Xg[b*96 + t] = pack_split(v0, v1);
    }
    if (idx < BB*2) g_lp[idx] = lp[idx];
}

// LSTM activations from split-K gate partials; writes hl float + hl-split
__global__ void act_kernel() {
    int idx = blockIdx.x * blockDim.x + threadIdx.x;
    if (idx >= BB*64) return;
    int r = idx >> 6, u2 = idx & 63, u = 2*u2;
    float hlv[2];
    #pragma unroll
    for (int d = 0; d < 2; d++) {
        int uu = u + d;
        float gi = g_part[r*512 + uu]       + g_part[BB*512 + r*512 + uu]       + g_biasg[uu];
        float gf = g_part[r*512 + uu + 128] + g_part[BB*512 + r*512 + uu + 128] + g_biasg[uu + 128];
        float gg = g_part[r*512 + uu + 256] + g_part[BB*512 + r*512 + uu + 256] + g_biasg[uu + 256];
        float go = g_part[r*512 + uu + 384] + g_part[BB*512 + r*512 + uu + 384] + g_biasg[uu + 384];
        float si = 1.f / (1.f + __expf(-gi));
        float sf = 1.f / (1.f + __expf(-gf));
        float so = 1.f / (1.f + __expf(-go));
        float cc = sf * g_c[r*128 + uu] + si * tanhf(gg);
        g_c[r*128 + uu] = cc;
        float hv = so * tanhf(cc);
        g_hl[r*128 + uu] = hv;
        hlv[d] = hv;
    }
    g_Xm1[r*576 + u2] = pack_split(hlv[0], hlv[1]);
}

// rel_pos, position update, rels output, next dec_in (split)
__global__ void posdec_kernel(const float* __restrict__ Wpos, const float* __restrict__ bpos,
                              const float* __restrict__ Wemb, const float* __restrict__ bemb,
                              float* __restrict__ rels_out, int step) {
    int b = blockIdx.x;
    int t = threadIdx.x;
    __shared__ float hr[128];
    __shared__ float sr[2];
    hr[t] = g_hl[b*128 + t];
    __syncthreads();
    int w = t >> 5, lane = t & 31;
    if (w < 2) {
        float part = 0.f;
        for (int k = lane; k < 128; k += 32) part += hr[k] * Wpos[w*128 + k];
        #pragma unroll
        for (int off = 16; off; off >>= 1) part += __shfl_down_sync(0xffffffffu, part, off);
        if (lane == 0) sr[w] = part + bpos[w];
    }
    __syncthreads();
    float ra = sr[0], rb = sr[1];
    if (t < 32) {
        int e0 = 2*t, e1 = 2*t + 1;
        float v0 = ra*Wemb[e0*2] + rb*Wemb[e0*2+1] + bemb[e0];
        float v1 = ra*Wemb[e1*2] + rb*Wemb[e1*2+1] + bemb[e1];
        g_Xg[b*96 + t] = pack_split(v0, v1);
    }
    if (t == 0) {
        rels_out[(step*BB + b)*2 + 0] = ra;
        rels_out[(step*BB + b)*2 + 1] = rb;
        g_lp[b*2 + 0] += ra;
        g_lp[b*2 + 1] += rb;
    }
}

// pool A build + split from hcon split-K partials (+biasc): row = g*576+i*24+j
__global__ void asplit_kernel() {
    int row = blockIdx.x;
    int grp = row / 576;
    int rem = row - grp*576;
    int i = rem / 24, j = rem - (rem/24)*24;
    int t = threadIdx.x;
    float pix = g_lp[(grp*24 + i)*2 + 0];
    float piy = g_lp[(grp*24 + i)*2 + 1];
    float pjx = g_lp[(grp*24 + j)*2 + 0];
    float pjy = g_lp[(grp*24 + j)*2 + 1];
    float dx = pjx - pix, dy = pjy - piy;
    float inv = 1.f / fmaxf(sqrtf(dx*dx + dy*dy), 1e-12f);
    float ra = dx * inv, rb = dy * inv;
    int k = t * 4;
    int base = (grp*24 + j)*512 + k;
    float4 hc = make_float4(0.f, 0.f, 0.f, 0.f);
    #pragma unroll
    for (int zz = 0; zz < 4; zz++) {
        const float4 p = *(const float4*)&g_part[zz*BB*512 + base];
        hc.x += p.x; hc.y += p.y; hc.z += p.z; hc.w += p.w;
    }
    const float4 bc = *(const float4*)&g_biasc[k];
    hc.x += bc.x; hc.y += bc.y; hc.z += bc.z; hc.w += bc.w;
    const float4 m0 = *(const float4*)&g_M0[k];
    const float4 m1 = *(const float4*)&g_M1[k];
    float v0 = fmaxf(fmaf(ra, m0.x, fmaf(rb, m1.x, hc.x)), 0.f);
    float v1 = fmaxf(fmaf(ra, m0.y, fmaf(rb, m1.y, hc.y)), 0.f);
    float v2 = fmaxf(fmaf(ra, m0.z, fmaf(rb, m1.z, hc.z)), 0.f);
    float v3 = fmaxf(fmaf(ra, m0.w, fmaf(rb, m1.w, hc.w)), 0.f);
    uint2 u0 = pack_split(v0, v1);
    uint2 u1 = pack_split(v2, v3);
    *(uint4*)&g_PAsp[(size_t)row*256 + 2*t] = make_uint4(u0.x, u0.y, u1.x, u1.y);
}

// h = relu(sum of mlp2 partials + bm2); writes h float + h-split for next gates
__global__ void finalize_kernel(const float* __restrict__ bm2) {
    int idx = blockIdx.x * blockDim.x + threadIdx.x;
    if (idx >= BB*64) return;
    int r = idx >> 6, u2 = idx & 63, u = 2*u2;
    float v[2];
    #pragma unroll
    for (int d = 0; d < 2; d++) {
        int uu = u + d;
        float s = bm2[uu];
        #pragma unroll
        for (int zz = 0; zz < 4; zz++) s += g_part[zz*BB*128 + r*128 + uu];
        v[d] = fmaxf(s, 0.f);
    }
    *(float2*)&g_h[r*128 + u] = make_float2(v[0], v[1]);
    g_Xg[r*96 + 32 + u2] = pack_split(v[0], v[1]);
}

__global__ void copyout_kernel(float* __restrict__ out) {
    int idx = blockIdx.x * blockDim.x + threadIdx.x;
    if (idx < BB*128) out[SEQ*BB*2 + idx] = g_h[idx];
}

// ---------------- launch -------------------------------------------------------
static void* sym_addr(const void* s) { void* p = nullptr; cudaGetSymbolAddress(&p, s); return p; }

extern "C" void kernel_launch(void* const* d_in, const int* in_sizes, int n_in,
                              void* d_out, int out_size) {
    const float* last_pos     = (const float*)d_in[0];
    const float* last_pos_rel = (const float*)d_in[1];
    const float* h0    = (const float*)d_in[2];
    const float* c0    = (const float*)d_in[3];
    const float* W_emb = (const float*)d_in[5];
    const float* b_emb = (const float*)d_in[6];
    const float* W_ih  = (const float*)d_in[7];
    const float* W_hh  = (const float*)d_in[8];
    const float* b_ih  = (const float*)d_in[9];
    const float* b_hh  = (const float*)d_in[10];
    const float* W_pos = (const float*)d_in[11];
    const float* b_pos = (const float*)d_in[12];
    const float* Wp_emb= (const float*)d_in[13];
    const float* bp_emb= (const float*)d_in[14];
    const float* Wp1   = (const float*)d_in[15];
    const float* bp1   = (const float*)d_in[16];
    const float* Wp2   = (const float*)d_in[17];
    const float* bp2   = (const float*)d_in[18];
    const float* Wm1   = (const float*)d_in[19];
    const float* bm1   = (const float*)d_in[20];
    const float* Wm2   = (const float*)d_in[21];
    const float* bm2   = (const float*)d_in[22];
    float* out = (float*)d_out;

    const int SMEMB = (3200 + 4224) * 8 + 4 * 128 * 4;   // 61440
    cudaFuncSetAttribute(hgemm_kernel, cudaFuncAttributeMaxDynamicSharedMemorySize, SMEMB);

    float* p_part  = (float*)sym_addr(g_part);
    uint2* p_Xg    = (uint2*)sym_addr(g_Xg);
    uint2* p_Xm1   = (uint2*)sym_addr(g_Xm1);
    uint2* p_Ysp   = (uint2*)sym_addr(g_Ysp);
    uint2* p_PAsp  = (uint2*)sym_addr(g_PAsp);
    uint2* p_Wgsp  = (uint2*)sym_addr(g_Wgsp);
    uint2* p_W1sp  = (uint2*)sym_addr(g_W1sp);
    uint2* p_Wp2sp = (uint2*)sym_addr(g_Wp2sp);
    uint2* p_Wm1sp = (uint2*)sym_addr(g_Wm1sp);
    uint2* p_Wm2sp = (uint2*)sym_addr(g_Wm2sp);

    precompute_kernel<<<2, 256>>>(Wp1, Wp_emb, bp_emb, bp1, b_ih, b_hh);
    splitw_kernel<<<(576*1024 + 255)/256, 256>>>(W_ih, W_hh, Wp1, Wp2, Wm1, Wm2);
    init_kernel<<<(BB*64 + 255)/256, 256>>>(h0, c0, last_pos, last_pos_rel, W_emb, b_emb);

    for (int s = 0; s < SEQ; s++) {
        // gates: [Xg(1536x96)] @ Wg^T -> partials (split-K 2)
        hgemm_kernel<<<dim3(4, 16, 2), 256, SMEMB>>>(
            p_Xg, 96, 48, p_Wgsp, 512, nullptr, p_part, 512, 4);
        act_kernel<<<384, 256>>>();
        posdec_kernel<<<BB, 128>>>(W_pos, b_pos, W_emb, b_emb, out, s);
        // hcon: hl-split (Xm1 cols 0..63) @ Wp1_h^T -> partials (split-K 4)
        hgemm_kernel<<<dim3(4, 16, 4), 256, SMEMB>>>(
            p_Xm1, 576, 16, p_W1sp, 512, nullptr, p_part, 512, 4);
        asplit_kernel<<<36864, 128>>>();
        // pool: [36864,512]@Wp2^T + bias + relu + max over j -> split into Xm1[64..575]
        hgemm_kernel<<<dim3(8, 384, 1), 256, SMEMB>>>(
            p_PAsp, 256, 256, p_Wp2sp, 1024, bp2, p_Xm1, 0, 2);
        // mlp1: Xm1(1536x576) @ Wm1^T + bm1, relu -> split store Ysp
        hgemm_kernel<<<dim3(8, 16, 1), 256, SMEMB>>>(
            p_Xm1, 576, 576, p_Wm1sp, 1024, bm1, p_Ysp, 1024, 3);
        // mlp2: Ysp(1536x512) @ Wm2^T -> partials (split-K 4)
        hgemm_kernel<<<dim3(1, 16, 4), 256, SMEMB>>>(
            p_Ysp, 512, 128, p_Wm2sp, 128, nullptr, p_part, 128, 4);
        finalize_kernel<<<384, 256>>>(bm2);
    }
    copyout_kernel<<<(BB*128 + 255)/256, 256>>>(out);
}